// round 2
// baseline (speedup 1.0000x reference)
#include <cuda_runtime.h>
#include <cstdint>

#define D 128
#define MAXN 40000
#define MAXE 640000

// Scratch (no allocations allowed -> device globals). 16B-aligned: we use
// vector (128-bit) loads/stores/reductions on all of these.
__device__ __align__(16) float g_AB[(size_t)MAXN * 256]; // [N][256]: 0..127 = nf@W1^T, 128..255 = nf@W2^T + b_e
__device__ __align__(16) float g_agg[(size_t)MAXN * D];  // segment sum of e over dst
__device__ __align__(16) float g_deg[MAXN];              // in-degree (float)
__device__ __align__(16) float g_WeT[384 * 128];         // W_e transposed: [k][n]
__device__ __align__(16) float g_WnT[256 * 128];         // W_n transposed: [k][n]

#define WPAD 132                              // k-major weight smem row stride (16B aligned, conflict free)
#define SMEM_GEMM ((128 * WPAD + 64 * 128) * 4)
#define SMEM_EDGE (SMEM_GEMM + 64 * 2 * 4)

// ---------------------------------------------------------------------------
__global__ void k_zero(int n_nodes) {
    int i = blockIdx.x * blockDim.x + threadIdx.x;
    int tot4 = n_nodes * (D / 4);
    if (i < tot4) reinterpret_cast<float4*>(g_agg)[i] = make_float4(0.f, 0.f, 0.f, 0.f);
    if (i < n_nodes) g_deg[i] = 0.f;
}

__global__ void k_transpose(const float* __restrict__ We, const float* __restrict__ Wn) {
    int i = blockIdx.x * blockDim.x + threadIdx.x;
    if (i < 128 * 384) {            // We: [128][384] row-major -> WeT[k][n]
        int n = i / 384, k = i % 384;
        g_WeT[k * 128 + n] = We[i];
    }
    if (i < 128 * 256) {            // Wn: [128][256] row-major -> WnT[k][n]
        int n = i / 256, k = i % 256;
        g_WnT[k * 128 + n] = Wn[i];
    }
}

// ---------------------------------------------------------------------------
// Shared GEMM pieces: 64(M) x 128(N) x 128(K) per block, 256 threads.
// Thread (ty = tid/32, tx = tid%32) owns rows ty*8..ty*8+7, cols tx*4..tx*4+3.

__device__ __forceinline__ void load_w(const float* __restrict__ gWT, float* Wsm, int tid) {
    // gWT is k-major [128][128]; store k-major with pad -> conflict-free LDS.128 later
    #pragma unroll
    for (int i = tid; i < 128 * 32; i += 256) {
        int k = i >> 5, q = i & 31;
        float4 v = *reinterpret_cast<const float4*>(gWT + k * 128 + q * 4);
        *reinterpret_cast<float4*>(Wsm + k * WPAD + q * 4) = v;
    }
}

__device__ __forceinline__ void load_in(const float* __restrict__ gIn, float* Insm,
                                        int mbase, int M, int tid) {
    #pragma unroll
    for (int i = tid; i < 64 * 32; i += 256) {
        int m = i >> 5, q = i & 31;
        float4 v = make_float4(0.f, 0.f, 0.f, 0.f);
        if (mbase + m < M)
            v = *reinterpret_cast<const float4*>(gIn + (size_t)(mbase + m) * D + q * 4);
        *reinterpret_cast<float4*>(Insm + m * D + q * 4) = v;
    }
}

__device__ __forceinline__ void mma_tile(const float* Insm, const float* Wsm,
                                         int ty, int tx, float4 acc[8]) {
    const float* inb = Insm + ty * 8 * D;
    const float* wb = Wsm + tx * 4;
    #pragma unroll 4
    for (int k = 0; k < 128; ++k) {
        float4 w = *reinterpret_cast<const float4*>(wb + k * WPAD);
        #pragma unroll
        for (int r = 0; r < 8; ++r) {
            float a = inb[r * D + k];          // warp-uniform -> LDS broadcast
            acc[r].x += a * w.x;
            acc[r].y += a * w.y;
            acc[r].z += a * w.z;
            acc[r].w += a * w.w;
        }
    }
}

// ---------------------------------------------------------------------------
// k1: A|B' precompute.  grid = (ceil(N/64), 2); half 0 -> A, half 1 -> B + b_e
__global__ void __launch_bounds__(256, 2)
k_pre(const float* __restrict__ nf, const float* __restrict__ b_e, int N) {
    extern __shared__ float smem[];
    float* Wsm  = smem;
    float* Insm = smem + 128 * WPAD;
    int tid = threadIdx.x, tx = tid & 31, ty = tid >> 5;
    int mbase = blockIdx.x * 64;
    int half = blockIdx.y;

    load_w(g_WeT + half * 128 * 128, Wsm, tid);
    load_in(nf, Insm, mbase, N, tid);
    __syncthreads();

    float4 acc[8];
    #pragma unroll
    for (int r = 0; r < 8; ++r) acc[r] = make_float4(0.f, 0.f, 0.f, 0.f);
    mma_tile(Insm, Wsm, ty, tx, acc);

    int c0 = tx * 4;
    float4 bias = make_float4(0.f, 0.f, 0.f, 0.f);
    if (half == 1) bias = *reinterpret_cast<const float4*>(b_e + c0);
    #pragma unroll
    for (int r = 0; r < 8; ++r) {
        int m = mbase + ty * 8 + r;
        if (m < N) {
            float4 v = make_float4(acc[r].x + bias.x, acc[r].y + bias.y,
                                   acc[r].z + bias.z, acc[r].w + bias.w);
            *reinterpret_cast<float4*>(g_AB + (size_t)m * 256 + half * 128 + c0) = v;
        }
    }
}

// ---------------------------------------------------------------------------
// k2: e = A[src] + B'[dst] + ef@W3^T ; write e ; scatter-add into agg/deg.
// NOTE: src/dst are int32 (JAX x64 disabled -> jnp.int64 materializes as int32).
__global__ void __launch_bounds__(256, 2)
k_edge(const float* __restrict__ ef, const int* __restrict__ src,
       const int* __restrict__ dst, float* __restrict__ e_out, int E) {
    extern __shared__ float smem[];
    float* Wsm  = smem;
    float* Insm = smem + 128 * WPAD;
    int* s_src = reinterpret_cast<int*>(Insm + 64 * D);
    int* s_dst = s_src + 64;
    int tid = threadIdx.x, tx = tid & 31, ty = tid >> 5;
    int mbase = blockIdx.x * 64;

    load_w(g_WeT + 256 * 128, Wsm, tid);
    load_in(ef, Insm, mbase, E, tid);
    if (tid < 64) {
        int m = mbase + tid;
        s_src[tid] = (m < E) ? src[m] : 0;
        s_dst[tid] = (m < E) ? dst[m] : 0;
    }
    __syncthreads();

    float4 acc[8];
    #pragma unroll
    for (int r = 0; r < 8; ++r) acc[r] = make_float4(0.f, 0.f, 0.f, 0.f);
    mma_tile(Insm, Wsm, ty, tx, acc);

    int c0 = tx * 4;
    #pragma unroll
    for (int r = 0; r < 8; ++r) {
        int m = mbase + ty * 8 + r;
        if (m < E) {
            int s = s_src[ty * 8 + r];
            int d = s_dst[ty * 8 + r];
            float4 a = *reinterpret_cast<const float4*>(g_AB + (size_t)s * 256 + c0);
            float4 b = *reinterpret_cast<const float4*>(g_AB + (size_t)d * 256 + 128 + c0);
            float4 v = make_float4(acc[r].x + a.x + b.x, acc[r].y + a.y + b.y,
                                   acc[r].z + a.z + b.z, acc[r].w + a.w + b.w);
            *reinterpret_cast<float4*>(e_out + (size_t)m * D + c0) = v;
            float* ap = g_agg + (size_t)d * D + c0;
            asm volatile("red.global.add.v4.f32 [%0], {%1,%2,%3,%4};"
                         :: "l"(ap), "f"(v.x), "f"(v.y), "f"(v.z), "f"(v.w)
                         : "memory");
            if (tx == 0) atomicAdd(&g_deg[d], 1.0f);
        }
    }
}

// ---------------------------------------------------------------------------
// k3: n = nf@Wn1^T + (agg_sum/max(deg,1))@Wn2^T + b_n
__global__ void __launch_bounds__(256, 2)
k_node(const float* __restrict__ nf, const float* __restrict__ b_n,
       float* __restrict__ n_out, int N) {
    extern __shared__ float smem[];
    float* Wsm  = smem;
    float* Insm = smem + 128 * WPAD;
    int tid = threadIdx.x, tx = tid & 31, ty = tid >> 5;
    int mbase = blockIdx.x * 64;

    float4 acc[8];
    #pragma unroll
    for (int r = 0; r < 8; ++r) acc[r] = make_float4(0.f, 0.f, 0.f, 0.f);

    // chunk 0: nf * Wn[:, :128]^T
    load_w(g_WnT, Wsm, tid);
    load_in(nf, Insm, mbase, N, tid);
    __syncthreads();
    mma_tile(Insm, Wsm, ty, tx, acc);
    __syncthreads();

    // chunk 1: agg * Wn[:, 128:]^T  (agg normalized on the fly)
    load_w(g_WnT + 128 * 128, Wsm, tid);
    #pragma unroll
    for (int i = tid; i < 64 * 32; i += 256) {
        int m = i >> 5, q = i & 31;
        float4 v = make_float4(0.f, 0.f, 0.f, 0.f);
        int gm = mbase + m;
        if (gm < N) {
            v = *reinterpret_cast<const float4*>(g_agg + (size_t)gm * D + q * 4);
            float inv = 1.0f / fmaxf(g_deg[gm], 1.0f);
            v.x *= inv; v.y *= inv; v.z *= inv; v.w *= inv;
        }
        *reinterpret_cast<float4*>(Insm + m * D + q * 4) = v;
    }
    __syncthreads();
    mma_tile(Insm, Wsm, ty, tx, acc);

    int c0 = tx * 4;
    float4 bias = *reinterpret_cast<const float4*>(b_n + c0);
    #pragma unroll
    for (int r = 0; r < 8; ++r) {
        int m = mbase + ty * 8 + r;
        if (m < N) {
            float4 v = make_float4(acc[r].x + bias.x, acc[r].y + bias.y,
                                   acc[r].z + bias.z, acc[r].w + bias.w);
            *reinterpret_cast<float4*>(n_out + (size_t)m * D + c0) = v;
        }
    }
}

// ---------------------------------------------------------------------------
extern "C" void kernel_launch(void* const* d_in, const int* in_sizes, int n_in,
                              void* d_out, int out_size) {
    const float* nf  = (const float*)d_in[0];
    const float* ef  = (const float*)d_in[1];
    const int*   src = (const int*)d_in[2];   // int32! (JAX x64 disabled)
    const int*   dst = (const int*)d_in[3];
    const float* We  = (const float*)d_in[4];
    const float* be  = (const float*)d_in[5];
    const float* Wn  = (const float*)d_in[6];
    const float* bn  = (const float*)d_in[7];

    int N = in_sizes[0] / D;
    int E = in_sizes[1] / D;

    float* n_out = (float*)d_out;                  // [N][128] first (tuple order)
    float* e_out = n_out + (size_t)N * D;          // [E][128]

    cudaFuncSetAttribute(k_pre,  cudaFuncAttributeMaxDynamicSharedMemorySize, SMEM_GEMM);
    cudaFuncSetAttribute(k_edge, cudaFuncAttributeMaxDynamicSharedMemorySize, SMEM_EDGE);
    cudaFuncSetAttribute(k_node, cudaFuncAttributeMaxDynamicSharedMemorySize, SMEM_GEMM);

    int zthreads = N * (D / 4);
    k_zero<<<(zthreads + 255) / 256, 256>>>(N);
    k_transpose<<<(128 * 384 + 255) / 256, 256>>>(We, Wn);

    dim3 g1((N + 63) / 64, 2);
    k_pre<<<g1, 256, SMEM_GEMM>>>(nf, be, N);
    k_edge<<<(E + 63) / 64, 256, SMEM_EDGE>>>(ef, src, dst, e_out, E);
    k_node<<<(N + 63) / 64, 256, SMEM_GEMM>>>(nf, bn, n_out, N);
}